// round 3
// baseline (speedup 1.0000x reference)
#include <cuda_runtime.h>
#include <cuda_bf16.h>
#include <cstdint>

// ============================================================================
// dims
// ============================================================================
#define B_DIM 32
#define F_DIM 1024
#define L_DIM 1000
#define N_DIM 2048
#define LPAD  1024

// GEMM tiling (per batch: M=N_DIM rows n, N=L cols l, K=F)
#define TM 128
#define TN 128
#define KC 32                    // K floats per stage
#define STAGES 3
#define KITERS (F_DIM / KC)      // 32

// SMEM: A stage = 128 rows x 36 floats (pad 32->36: conflict-free frag LDS)
#define ROWSTRIDE 36
#define STAGE_FLOATS (128 * ROWSTRIDE)                    // 4608
#define SMEM_FLOATS (2 * STAGES * STAGE_FLOATS)           // 27648
#define SMEM_BYTES  (SMEM_FLOATS * 4)                     // 110592

// ============================================================================
// device scratch (static globals: allocation-guard safe)
// ============================================================================
__device__ __align__(1024) float g_A [(size_t)N_DIM * F_DIM];        // 8 MB
__device__ __align__(1024) float g_Xt[(size_t)B_DIM * LPAD * F_DIM]; // 134 MB

// ============================================================================
// helpers
// ============================================================================
__device__ __forceinline__ float to_tf32(float x) {
    uint32_t r;
    asm("cvt.rna.tf32.f32 %0, %1;" : "=r"(r) : "f"(x));
    return __uint_as_float(r);
}

__device__ __forceinline__ uint32_t smem_u32(const void* p) {
    uint32_t a;
    asm("{ .reg .u64 t; cvta.to.shared.u64 t, %1; cvt.u32.u64 %0, t; }"
        : "=r"(a) : "l"(p));
    return a;
}

#define CP_ASYNC16(dst, src) \
    asm volatile("cp.async.cg.shared.global [%0], [%1], 16;" \
                 :: "r"(dst), "l"(src) : "memory")
#define CP_COMMIT() asm volatile("cp.async.commit_group;" ::: "memory")
#define CP_WAIT(n)  asm volatile("cp.async.wait_group %0;" :: "n"(n) : "memory")

__device__ __forceinline__ void mma_tf32(float d[4],
                                         uint32_t a0, uint32_t a1,
                                         uint32_t a2, uint32_t a3,
                                         uint32_t b0, uint32_t b1) {
    asm volatile(
        "mma.sync.aligned.m16n8k8.row.col.f32.tf32.tf32.f32 "
        "{%0, %1, %2, %3}, {%4, %5, %6, %7}, {%8, %9}, {%0, %1, %2, %3};"
        : "+f"(d[0]), "+f"(d[1]), "+f"(d[2]), "+f"(d[3])
        : "r"(a0), "r"(a1), "r"(a2), "r"(a3), "r"(b0), "r"(b1));
}

// ============================================================================
// prep 1: A[n][f] = tf32(C[f][n] * W[n])
// ============================================================================
__global__ void prep_a_kernel(const float* __restrict__ C,
                              const float* __restrict__ W) {
    __shared__ float tile[32][33];
    const int n0 = blockIdx.x * 32;
    const int f0 = blockIdx.y * 32;
    const int tx = threadIdx.x, ty = threadIdx.y;
    const float w = W[n0 + tx];
#pragma unroll
    for (int i = 0; i < 32; i += 8)
        tile[ty + i][tx] = C[(size_t)(f0 + ty + i) * N_DIM + n0 + tx] * w;
    __syncthreads();
#pragma unroll
    for (int i = 0; i < 32; i += 8)
        g_A[(size_t)(n0 + ty + i) * F_DIM + f0 + tx] = to_tf32(tile[tx][ty + i]);
}

// ============================================================================
// prep 2: Xt[b][l][f] = tf32(X[b][f][l]), l zero-padded to 1024
// ============================================================================
__global__ void prep_x_kernel(const float* __restrict__ X) {
    __shared__ float tile[32][33];
    const int l0 = blockIdx.x * 32;
    const int f0 = blockIdx.y * 32;
    const int b  = blockIdx.z;
    const int tx = threadIdx.x, ty = threadIdx.y;
    const float* Xb = X + (size_t)b * F_DIM * L_DIM;
#pragma unroll
    for (int i = 0; i < 32; i += 8) {
        int l = l0 + tx;
        tile[ty + i][tx] = (l < L_DIM)
            ? Xb[(size_t)(f0 + ty + i) * L_DIM + l] : 0.0f;
    }
    __syncthreads();
    float* Xtb = g_Xt + (size_t)b * LPAD * F_DIM;
#pragma unroll
    for (int i = 0; i < 32; i += 8)
        Xtb[(size_t)(l0 + ty + i) * F_DIM + f0 + tx] = to_tf32(tile[tx][ty + i]);
}

// ============================================================================
// GEMM: out[b, n0:n0+128, l0:l0+128] = A[n0:,:] x Xt[b, l0:, :]^T
//   256 threads = 8 warps; warp tile 32(m) x 64(n)
//   mma.sync m16n8k8 tf32, 3-stage cp.async pipeline
// ============================================================================
__global__ void __launch_bounds__(256, 1)
gemm_kernel(float* __restrict__ out) {
    extern __shared__ __align__(16) float smem[];

    const int tid = threadIdx.x;
    const int wid = tid >> 5;
    const int lid = tid & 31;
    const int g = lid >> 2;          // groupID   (fragment row index)
    const int t = lid & 3;           // threadID_in_group

    const int wm = wid & 3;          // warp m block (0..3) -> 32 rows each
    const int wn = wid >> 2;         // warp n block (0..1) -> 64 cols each

    const int n0 = blockIdx.x * TM;
    const int l0 = blockIdx.y * TN;
    const int b  = blockIdx.z;

    const float* Abase = g_A  + (size_t)n0 * F_DIM;
    const float* Bbase = g_Xt + ((size_t)b * LPAD + l0) * F_DIM;

    // accumulators: 2 m16 blocks x 8 n8 blocks x 4 regs
    float d[2][8][4];
#pragma unroll
    for (int mi = 0; mi < 2; mi++)
#pragma unroll
        for (int ni = 0; ni < 8; ni++)
#pragma unroll
            for (int r = 0; r < 4; r++) d[mi][ni][r] = 0.0f;

    // ---- cp.async loaders (each thread: 4 A chunks + 4 B chunks of 16B) ----
    const int c_row = tid >> 3;        // 0..31 base row; +32 per i
    const int c_cb  = tid & 7;         // 16B chunk within 128B row
    const uint32_t sbase = smem_u32(smem);

    auto load_stage = [&](int s, int k) {
        const int k0 = k * KC;
        const uint32_t sa = sbase + (uint32_t)(s * STAGE_FLOATS) * 4;
        const uint32_t sb = sbase + (uint32_t)((STAGES + s) * STAGE_FLOATS) * 4;
#pragma unroll
        for (int i = 0; i < 4; i++) {
            int row = c_row + i * 32;
            CP_ASYNC16(sa + (uint32_t)(row * ROWSTRIDE + c_cb * 4) * 4,
                       Abase + (size_t)row * F_DIM + k0 + c_cb * 4);
        }
#pragma unroll
        for (int i = 0; i < 4; i++) {
            int row = c_row + i * 32;
            CP_ASYNC16(sb + (uint32_t)(row * ROWSTRIDE + c_cb * 4) * 4,
                       Bbase + (size_t)row * F_DIM + k0 + c_cb * 4);
        }
    };

    // prologue: stages 0, 1
    load_stage(0, 0); CP_COMMIT();
    load_stage(1, 1); CP_COMMIT();

    for (int k = 0; k < KITERS; k++) {
        if (k > 0) __syncthreads();      // buffer (k+2)%3 was consumed at k-1
        if (k + 2 < KITERS) load_stage((k + 2) % STAGES, k + 2);
        CP_COMMIT();
        CP_WAIT(2);                      // stage k groups complete
        __syncthreads();

        const float* As = smem + (k % STAGES) * STAGE_FLOATS;
        const float* Bs = smem + (STAGES + (k % STAGES)) * STAGE_FLOATS;

#pragma unroll
        for (int kk = 0; kk < 4; kk++) {
            const int kc = kk * 8;
            // B fragments (shared across both mi blocks)
            uint32_t bf[8][2];
#pragma unroll
            for (int ni = 0; ni < 8; ni++) {
                const float* bp = Bs + (wn * 64 + ni * 8 + g) * ROWSTRIDE + kc;
                bf[ni][0] = __float_as_uint(bp[t]);
                bf[ni][1] = __float_as_uint(bp[t + 4]);
            }
#pragma unroll
            for (int mi = 0; mi < 2; mi++) {
                const float* ap = As + (wm * 32 + mi * 16 + g) * ROWSTRIDE + kc;
                uint32_t a0 = __float_as_uint(ap[t]);
                uint32_t a2 = __float_as_uint(ap[t + 4]);
                uint32_t a1 = __float_as_uint(ap[8 * ROWSTRIDE + t]);
                uint32_t a3 = __float_as_uint(ap[8 * ROWSTRIDE + t + 4]);
#pragma unroll
                for (int ni = 0; ni < 8; ni++)
                    mma_tf32(d[mi][ni], a0, a1, a2, a3, bf[ni][0], bf[ni][1]);
            }
        }
    }

    // ---- epilogue: direct global stores (pairs never straddle L=1000) ----
#pragma unroll
    for (int mi = 0; mi < 2; mi++) {
        const int row = n0 + wm * 32 + mi * 16 + g;
        float* r0 = out + ((size_t)b * N_DIM + row) * L_DIM;
        float* r1 = r0 + 8 * L_DIM;
#pragma unroll
        for (int ni = 0; ni < 8; ni++) {
            const int l = l0 + wn * 64 + ni * 8 + 2 * t;
            if (l < L_DIM) {
                *reinterpret_cast<float2*>(r0 + l) =
                    make_float2(d[mi][ni][0], d[mi][ni][1]);
                *reinterpret_cast<float2*>(r1 + l) =
                    make_float2(d[mi][ni][2], d[mi][ni][3]);
            }
        }
    }
}

// ============================================================================
// host
// ============================================================================
extern "C" void kernel_launch(void* const* d_in, const int* in_sizes, int n_in,
                              void* d_out, int out_size) {
    const float* X = (const float*)d_in[0];
    const float* C = (const float*)d_in[1];
    const float* W = (const float*)d_in[2];
    for (int i = 0; i < n_in; i++) {
        if (in_sizes[i] == B_DIM * F_DIM * L_DIM) X = (const float*)d_in[i];
        else if (in_sizes[i] == F_DIM * N_DIM)    C = (const float*)d_in[i];
        else if (in_sizes[i] == N_DIM)            W = (const float*)d_in[i];
    }

    cudaFuncSetAttribute(gemm_kernel,
                         cudaFuncAttributeMaxDynamicSharedMemorySize, SMEM_BYTES);

    prep_a_kernel<<<dim3(N_DIM / 32, F_DIM / 32), dim3(32, 8)>>>(C, W);
    prep_x_kernel<<<dim3(LPAD / 32, F_DIM / 32, B_DIM), dim3(32, 8)>>>(X);
    gemm_kernel<<<dim3(N_DIM / TM, LPAD / TN, B_DIM), 256, SMEM_BYTES>>>(
        (float*)d_out);
}

// round 4
// speedup vs baseline: 1.6671x; 1.6671x over previous
#include <cuda_runtime.h>
#include <cuda_fp16.h>
#include <cstdint>

// ============================================================================
// dims
// ============================================================================
#define B_DIM 32
#define F_DIM 1024
#define L_DIM 1000
#define N_DIM 2048
#define LPAD  1024

// GEMM tiling (per batch: M=N_DIM rows n, N=L cols l, K=F)
#define TM 256
#define TN 128
#define KC 32                    // K halves per stage (64B rows)
#define STAGES 3
#define KITERS (F_DIM / KC)      // 32

// SMEM: padded row stride 40 halves = 80B -> ldmatrix conflict-free
#define RSTRIDE_B 80
#define A_STAGE_BYTES (TM * RSTRIDE_B)                     // 20480
#define B_STAGE_BYTES (TN * RSTRIDE_B)                     // 10240
#define STAGE_BYTES (A_STAGE_BYTES + B_STAGE_BYTES)        // 30720
#define SMEM_BYTES (STAGES * STAGE_BYTES)                  // 92160

// ============================================================================
// device scratch (static globals: allocation-guard safe)
// ============================================================================
__device__ __align__(1024) __half g_A [(size_t)N_DIM * F_DIM];        // 4 MB
__device__ __align__(1024) __half g_Xt[(size_t)B_DIM * LPAD * F_DIM]; // 67 MB

// ============================================================================
// helpers
// ============================================================================
__device__ __forceinline__ uint32_t smem_u32(const void* p) {
    uint32_t a;
    asm("{ .reg .u64 t; cvta.to.shared.u64 t, %1; cvt.u32.u64 %0, t; }"
        : "=r"(a) : "l"(p));
    return a;
}

#define CP_ASYNC16(dst, src) \
    asm volatile("cp.async.cg.shared.global [%0], [%1], 16;" \
                 :: "r"(dst), "l"(src) : "memory")
#define CP_COMMIT() asm volatile("cp.async.commit_group;" ::: "memory")
#define CP_WAIT(n)  asm volatile("cp.async.wait_group %0;" :: "n"(n) : "memory")

#define LDSM_X4(r0, r1, r2, r3, addr) \
    asm volatile("ldmatrix.sync.aligned.m8n8.x4.shared.b16 {%0,%1,%2,%3}, [%4];" \
                 : "=r"(r0), "=r"(r1), "=r"(r2), "=r"(r3) : "r"(addr))

__device__ __forceinline__ void mma_f16(float d[4],
                                        uint32_t a0, uint32_t a1,
                                        uint32_t a2, uint32_t a3,
                                        uint32_t b0, uint32_t b1) {
    asm volatile(
        "mma.sync.aligned.m16n8k16.row.col.f32.f16.f16.f32 "
        "{%0, %1, %2, %3}, {%4, %5, %6, %7}, {%8, %9}, {%0, %1, %2, %3};"
        : "+f"(d[0]), "+f"(d[1]), "+f"(d[2]), "+f"(d[3])
        : "r"(a0), "r"(a1), "r"(a2), "r"(a3), "r"(b0), "r"(b1));
}

// ============================================================================
// prep 1: A[n][f] = fp16(C[f][n] * W[n])
// ============================================================================
__global__ void prep_a_kernel(const float* __restrict__ C,
                              const float* __restrict__ W) {
    __shared__ float tile[32][33];
    const int n0 = blockIdx.x * 32;
    const int f0 = blockIdx.y * 32;
    const int tx = threadIdx.x, ty = threadIdx.y;
    const float w = W[n0 + tx];
#pragma unroll
    for (int i = 0; i < 32; i += 8)
        tile[ty + i][tx] = C[(size_t)(f0 + ty + i) * N_DIM + n0 + tx] * w;
    __syncthreads();
    // write half2: threads tx<16 cover f-pairs
    if (tx < 16) {
#pragma unroll
        for (int i = 0; i < 32; i += 8) {
            const int n = n0 + ty + i;
            __half2 v = __floats2half2_rn(tile[2 * tx][ty + i],
                                          tile[2 * tx + 1][ty + i]);
            *reinterpret_cast<__half2*>(g_A + (size_t)n * F_DIM + f0 + 2 * tx) = v;
        }
    }
}

// ============================================================================
// prep 2: Xt[b][l][f] = fp16(X[b][f][l]), l zero-padded to 1024
// ============================================================================
__global__ void prep_x_kernel(const float* __restrict__ X) {
    __shared__ float tile[32][33];
    const int l0 = blockIdx.x * 32;
    const int f0 = blockIdx.y * 32;
    const int b  = blockIdx.z;
    const int tx = threadIdx.x, ty = threadIdx.y;
    const float* Xb = X + (size_t)b * F_DIM * L_DIM;
#pragma unroll
    for (int i = 0; i < 32; i += 8) {
        int l = l0 + tx;
        tile[ty + i][tx] = (l < L_DIM)
            ? Xb[(size_t)(f0 + ty + i) * L_DIM + l] : 0.0f;
    }
    __syncthreads();
    __half* Xtb = g_Xt + (size_t)b * LPAD * F_DIM;
    if (tx < 16) {
#pragma unroll
        for (int i = 0; i < 32; i += 8) {
            const int l = l0 + ty + i;
            __half2 v = __floats2half2_rn(tile[2 * tx][ty + i],
                                          tile[2 * tx + 1][ty + i]);
            *reinterpret_cast<__half2*>(Xtb + (size_t)l * F_DIM + f0 + 2 * tx) = v;
        }
    }
}

// ============================================================================
// GEMM: out[b, n0:n0+256, l0:l0+128] = A x Xt^T
//   256 threads = 8 warps: 4(m) x 2(n), warp tile 64 x 64
//   mma m16n8k16 f16.f32, ldmatrix fragments, 3-stage cp.async
// ============================================================================
__global__ void __launch_bounds__(256, 1)
gemm_kernel(float* __restrict__ out) {
    extern __shared__ __align__(128) char smem[];
    const uint32_t sbase = smem_u32(smem);

    const int tid = threadIdx.x;
    const int wid = tid >> 5;
    const int lid = tid & 31;
    const int g = lid >> 2;
    const int t = lid & 3;

    const int wm = wid & 3;          // 0..3 -> 64 m-rows each
    const int wn = wid >> 2;         // 0..1 -> 64 n-cols each

    const int n0 = blockIdx.x * TM;
    const int l0 = blockIdx.y * TN;
    const int b  = blockIdx.z;

    const __half* Abase = g_A  + (size_t)n0 * F_DIM;
    const __half* Bbase = g_Xt + ((size_t)b * LPAD + l0) * F_DIM;

    float d[4][8][4];
#pragma unroll
    for (int mi = 0; mi < 4; mi++)
#pragma unroll
        for (int ni = 0; ni < 8; ni++)
#pragma unroll
            for (int r = 0; r < 4; r++) d[mi][ni][r] = 0.0f;

    // cp.async mapping: 16B chunk = 8 halves; 4 chunks per 64B row
    const int c_row = tid >> 2;      // base row (A: +64/iter, B: +64/iter)
    const int c_cb  = tid & 3;

    auto load_stage = [&](int s, int k) {
        const int k0 = k * KC;
        const uint32_t sa = sbase + s * STAGE_BYTES;
        const uint32_t sb = sa + A_STAGE_BYTES;
#pragma unroll
        for (int i = 0; i < 4; i++) {            // A: 256 rows
            int row = c_row + i * 64;
            CP_ASYNC16(sa + row * RSTRIDE_B + c_cb * 16,
                       Abase + (size_t)row * F_DIM + k0 + c_cb * 8);
        }
#pragma unroll
        for (int i = 0; i < 2; i++) {            // B: 128 rows
            int row = c_row + i * 64;
            CP_ASYNC16(sb + row * RSTRIDE_B + c_cb * 16,
                       Bbase + (size_t)row * F_DIM + k0 + c_cb * 8);
        }
    };

    load_stage(0, 0); CP_COMMIT();
    load_stage(1, 1); CP_COMMIT();

    // ldmatrix source addresses (per lane)
    const int lrow = lid & 15;
    const int lchunk = (lid >> 4) * 16;

    for (int k = 0; k < KITERS; k++) {
        if (k > 0) __syncthreads();
        if (k + 2 < KITERS) load_stage((k + 2) % STAGES, k + 2);
        CP_COMMIT();
        CP_WAIT(2);
        __syncthreads();

        const uint32_t sa = sbase + (k % STAGES) * STAGE_BYTES;
        const uint32_t sb = sa + A_STAGE_BYTES;

#pragma unroll
        for (int kk = 0; kk < 2; kk++) {
            const uint32_t koff = kk * 32 + lchunk;  // 16 halves per k16 step
            uint32_t af[4][4];
#pragma unroll
            for (int mi = 0; mi < 4; mi++) {
                uint32_t addr = sa + (wm * 64 + mi * 16 + lrow) * RSTRIDE_B + koff;
                LDSM_X4(af[mi][0], af[mi][1], af[mi][2], af[mi][3], addr);
            }
            uint32_t bf[8][2];
#pragma unroll
            for (int p = 0; p < 4; p++) {
                uint32_t addr = sb + (wn * 64 + p * 16 + lrow) * RSTRIDE_B + koff;
                uint32_t m0, m1, m2, m3;
                LDSM_X4(m0, m1, m2, m3, addr);
                bf[2 * p][0] = m0; bf[2 * p][1] = m2;
                bf[2 * p + 1][0] = m1; bf[2 * p + 1][1] = m3;
            }
#pragma unroll
            for (int mi = 0; mi < 4; mi++)
#pragma unroll
                for (int ni = 0; ni < 8; ni++)
                    mma_f16(d[mi][ni], af[mi][0], af[mi][1], af[mi][2], af[mi][3],
                            bf[ni][0], bf[ni][1]);
        }
    }

    // ---- epilogue: direct global float2 stores ----
#pragma unroll
    for (int mi = 0; mi < 4; mi++) {
        const int row = n0 + wm * 64 + mi * 16 + g;
        float* r0 = out + ((size_t)b * N_DIM + row) * L_DIM;
        float* r1 = r0 + 8 * L_DIM;
#pragma unroll
        for (int ni = 0; ni < 8; ni++) {
            const int l = l0 + wn * 64 + ni * 8 + 2 * t;
            if (l < L_DIM) {
                *reinterpret_cast<float2*>(r0 + l) =
                    make_float2(d[mi][ni][0], d[mi][ni][1]);
                *reinterpret_cast<float2*>(r1 + l) =
                    make_float2(d[mi][ni][2], d[mi][ni][3]);
            }
        }
    }
}

// ============================================================================
// host
// ============================================================================
extern "C" void kernel_launch(void* const* d_in, const int* in_sizes, int n_in,
                              void* d_out, int out_size) {
    const float* X = (const float*)d_in[0];
    const float* C = (const float*)d_in[1];
    const float* W = (const float*)d_in[2];
    for (int i = 0; i < n_in; i++) {
        if (in_sizes[i] == B_DIM * F_DIM * L_DIM) X = (const float*)d_in[i];
        else if (in_sizes[i] == F_DIM * N_DIM)    C = (const float*)d_in[i];
        else if (in_sizes[i] == N_DIM)            W = (const float*)d_in[i];
    }

    cudaFuncSetAttribute(gemm_kernel,
                         cudaFuncAttributeMaxDynamicSharedMemorySize, SMEM_BYTES);

    prep_a_kernel<<<dim3(N_DIM / 32, F_DIM / 32), dim3(32, 8)>>>(C, W);
    prep_x_kernel<<<dim3(LPAD / 32, F_DIM / 32, B_DIM), dim3(32, 8)>>>(X);
    gemm_kernel<<<dim3(N_DIM / TM, LPAD / TN, B_DIM), 256, SMEM_BYTES>>>(
        (float*)d_out);
}

// round 5
// speedup vs baseline: 1.8232x; 1.0936x over previous
#include <cuda_runtime.h>
#include <cuda_fp16.h>
#include <cstdint>

// ============================================================================
// dims
// ============================================================================
#define B_DIM 32
#define F_DIM 1024
#define L_DIM 1000
#define N_DIM 2048
#define LPAD  1024

// GEMM tiling (per batch: M=N_DIM rows n, N=L cols l, K=F)
#define TM 128
#define TN 128
#define KC 32                    // K halves per stage (64B rows)
#define STAGES 4
#define KITERS (F_DIM / KC)      // 32

// SMEM: padded row stride 40 halves = 80B -> ldmatrix conflict-free
#define RSTRIDE_B 80
#define A_STAGE_BYTES (TM * RSTRIDE_B)                     // 10240
#define B_STAGE_BYTES (TN * RSTRIDE_B)                     // 10240
#define STAGE_BYTES (A_STAGE_BYTES + B_STAGE_BYTES)        // 20480
#define SMEM_BYTES (STAGES * STAGE_BYTES)                  // 81920

// ============================================================================
// device scratch (static globals: allocation-guard safe)
// ============================================================================
__device__ __align__(1024) __half g_A [(size_t)N_DIM * F_DIM];        // 4 MB
__device__ __align__(1024) __half g_Xt[(size_t)B_DIM * LPAD * F_DIM]; // 67 MB

// ============================================================================
// helpers
// ============================================================================
__device__ __forceinline__ uint32_t smem_u32(const void* p) {
    uint32_t a;
    asm("{ .reg .u64 t; cvta.to.shared.u64 t, %1; cvt.u32.u64 %0, t; }"
        : "=r"(a) : "l"(p));
    return a;
}

#define CP_ASYNC16(dst, src) \
    asm volatile("cp.async.cg.shared.global [%0], [%1], 16;" \
                 :: "r"(dst), "l"(src) : "memory")
#define CP_COMMIT() asm volatile("cp.async.commit_group;" ::: "memory")
#define CP_WAIT(n)  asm volatile("cp.async.wait_group %0;" :: "n"(n) : "memory")

#define LDSM_X4(r0, r1, r2, r3, addr) \
    asm volatile("ldmatrix.sync.aligned.m8n8.x4.shared.b16 {%0,%1,%2,%3}, [%4];" \
                 : "=r"(r0), "=r"(r1), "=r"(r2), "=r"(r3) : "r"(addr))

__device__ __forceinline__ void mma_f16(float d[4],
                                        uint32_t a0, uint32_t a1,
                                        uint32_t a2, uint32_t a3,
                                        uint32_t b0, uint32_t b1) {
    asm volatile(
        "mma.sync.aligned.m16n8k16.row.col.f32.f16.f16.f32 "
        "{%0, %1, %2, %3}, {%4, %5, %6, %7}, {%8, %9}, {%0, %1, %2, %3};"
        : "+f"(d[0]), "+f"(d[1]), "+f"(d[2]), "+f"(d[3])
        : "r"(a0), "r"(a1), "r"(a2), "r"(a3), "r"(b0), "r"(b1));
}

// ============================================================================
// prep 1: A[n][f] = fp16(C[f][n] * W[n])
// ============================================================================
__global__ void prep_a_kernel(const float* __restrict__ C,
                              const float* __restrict__ W) {
    __shared__ float tile[32][33];
    const int n0 = blockIdx.x * 32;
    const int f0 = blockIdx.y * 32;
    const int tx = threadIdx.x, ty = threadIdx.y;
    const float w = W[n0 + tx];
#pragma unroll
    for (int i = 0; i < 32; i += 8)
        tile[ty + i][tx] = C[(size_t)(f0 + ty + i) * N_DIM + n0 + tx] * w;
    __syncthreads();
    if (tx < 16) {
#pragma unroll
        for (int i = 0; i < 32; i += 8) {
            const int n = n0 + ty + i;
            __half2 v = __floats2half2_rn(tile[2 * tx][ty + i],
                                          tile[2 * tx + 1][ty + i]);
            *reinterpret_cast<__half2*>(g_A + (size_t)n * F_DIM + f0 + 2 * tx) = v;
        }
    }
}

// ============================================================================
// prep 2: Xt[b][l][f] = fp16(X[b][f][l]), l zero-padded to 1024
// ============================================================================
__global__ void prep_x_kernel(const float* __restrict__ X) {
    __shared__ float tile[32][33];
    const int l0 = blockIdx.x * 32;
    const int f0 = blockIdx.y * 32;
    const int b  = blockIdx.z;
    const int tx = threadIdx.x, ty = threadIdx.y;
    const float* Xb = X + (size_t)b * F_DIM * L_DIM;
#pragma unroll
    for (int i = 0; i < 32; i += 8) {
        int l = l0 + tx;
        tile[ty + i][tx] = (l < L_DIM)
            ? Xb[(size_t)(f0 + ty + i) * L_DIM + l] : 0.0f;
    }
    __syncthreads();
    __half* Xtb = g_Xt + (size_t)b * LPAD * F_DIM;
    if (tx < 16) {
#pragma unroll
        for (int i = 0; i < 32; i += 8) {
            const int l = l0 + ty + i;
            __half2 v = __floats2half2_rn(tile[2 * tx][ty + i],
                                          tile[2 * tx + 1][ty + i]);
            *reinterpret_cast<__half2*>(Xtb + (size_t)l * F_DIM + f0 + 2 * tx) = v;
        }
    }
}

// ============================================================================
// GEMM: out[b, n0:n0+128, l0:l0+128] = A x Xt^T
//   128 threads = 4 warps: 2(m) x 2(n), warp tile 64 x 64
//   mma m16n8k16 f16.f32, ldmatrix fragments, 4-stage cp.async,
//   one __syncthreads per k-chunk, 2 CTAs per SM
// ============================================================================
__global__ void __launch_bounds__(128, 2)
gemm_kernel(float* __restrict__ out) {
    extern __shared__ __align__(128) char smem[];
    const uint32_t sbase = smem_u32(smem);

    const int tid = threadIdx.x;
    const int wid = tid >> 5;
    const int lid = tid & 31;
    const int g = lid >> 2;
    const int t = lid & 3;

    const int wm = wid & 1;          // 0..1 -> 64 m-rows each
    const int wn = wid >> 1;         // 0..1 -> 64 n-cols each

    const int n0 = blockIdx.x * TM;
    const int l0 = blockIdx.y * TN;
    const int b  = blockIdx.z;

    const __half* Abase = g_A  + (size_t)n0 * F_DIM;
    const __half* Bbase = g_Xt + ((size_t)b * LPAD + l0) * F_DIM;

    float d[4][8][4];
#pragma unroll
    for (int mi = 0; mi < 4; mi++)
#pragma unroll
        for (int ni = 0; ni < 8; ni++)
#pragma unroll
            for (int r = 0; r < 4; r++) d[mi][ni][r] = 0.0f;

    // cp.async mapping: 128 threads cover 128 rows x 4 chunks (16B) per matrix
    const int c_row = tid >> 2;      // 0..31, +32 per i
    const int c_cb  = tid & 3;

    auto load_stage = [&](int s, int k) {
        const int k0 = k * KC;
        const uint32_t sa = sbase + s * STAGE_BYTES;
        const uint32_t sb = sa + A_STAGE_BYTES;
#pragma unroll
        for (int i = 0; i < 4; i++) {
            int row = c_row + i * 32;
            CP_ASYNC16(sa + row * RSTRIDE_B + c_cb * 16,
                       Abase + (size_t)row * F_DIM + k0 + c_cb * 8);
        }
#pragma unroll
        for (int i = 0; i < 4; i++) {
            int row = c_row + i * 32;
            CP_ASYNC16(sb + row * RSTRIDE_B + c_cb * 16,
                       Bbase + (size_t)row * F_DIM + k0 + c_cb * 8);
        }
        CP_COMMIT();
    };

    // prologue: stages 0..2
    load_stage(0, 0);
    load_stage(1, 1);
    load_stage(2, 2);

    const int lrow = lid & 15;
    const int lchunk = (lid >> 4) * 16;

    for (int k = 0; k < KITERS; k++) {
        CP_WAIT(2);                  // stage k resident
        __syncthreads();             // all warps done with stage (k-1)%4
        if (k + 3 < KITERS) load_stage((k + 3) % STAGES, k + 3);

        const uint32_t sa = sbase + (k % STAGES) * STAGE_BYTES;
        const uint32_t sb = sa + A_STAGE_BYTES;

#pragma unroll
        for (int kk = 0; kk < 2; kk++) {
            const uint32_t koff = kk * 32 + lchunk;
            uint32_t af[4][4];
#pragma unroll
            for (int mi = 0; mi < 4; mi++) {
                uint32_t addr = sa + (wm * 64 + mi * 16 + lrow) * RSTRIDE_B + koff;
                LDSM_X4(af[mi][0], af[mi][1], af[mi][2], af[mi][3], addr);
            }
            uint32_t bf[8][2];
#pragma unroll
            for (int p = 0; p < 4; p++) {
                uint32_t addr = sb + (wn * 64 + p * 16 + lrow) * RSTRIDE_B + koff;
                uint32_t m0, m1, m2, m3;
                LDSM_X4(m0, m1, m2, m3, addr);
                bf[2 * p][0] = m0; bf[2 * p][1] = m2;
                bf[2 * p + 1][0] = m1; bf[2 * p + 1][1] = m3;
            }
#pragma unroll
            for (int mi = 0; mi < 4; mi++)
#pragma unroll
                for (int ni = 0; ni < 8; ni++)
                    mma_f16(d[mi][ni], af[mi][0], af[mi][1], af[mi][2], af[mi][3],
                            bf[ni][0], bf[ni][1]);
        }
    }

    // ---- epilogue: direct global float2 stores ----
#pragma unroll
    for (int mi = 0; mi < 4; mi++) {
        const int row = n0 + wm * 64 + mi * 16 + g;
        float* r0 = out + ((size_t)b * N_DIM + row) * L_DIM;
        float* r1 = r0 + 8 * L_DIM;
#pragma unroll
        for (int ni = 0; ni < 8; ni++) {
            const int l = l0 + wn * 64 + ni * 8 + 2 * t;
            if (l < L_DIM) {
                *reinterpret_cast<float2*>(r0 + l) =
                    make_float2(d[mi][ni][0], d[mi][ni][1]);
                *reinterpret_cast<float2*>(r1 + l) =
                    make_float2(d[mi][ni][2], d[mi][ni][3]);
            }
        }
    }
}

// ============================================================================
// host
// ============================================================================
extern "C" void kernel_launch(void* const* d_in, const int* in_sizes, int n_in,
                              void* d_out, int out_size) {
    const float* X = (const float*)d_in[0];
    const float* C = (const float*)d_in[1];
    const float* W = (const float*)d_in[2];
    for (int i = 0; i < n_in; i++) {
        if (in_sizes[i] == B_DIM * F_DIM * L_DIM) X = (const float*)d_in[i];
        else if (in_sizes[i] == F_DIM * N_DIM)    C = (const float*)d_in[i];
        else if (in_sizes[i] == N_DIM)            W = (const float*)d_in[i];
    }

    cudaFuncSetAttribute(gemm_kernel,
                         cudaFuncAttributeMaxDynamicSharedMemorySize, SMEM_BYTES);

    prep_a_kernel<<<dim3(N_DIM / 32, F_DIM / 32), dim3(32, 8)>>>(C, W);
    prep_x_kernel<<<dim3(LPAD / 32, F_DIM / 32, B_DIM), dim3(32, 8)>>>(X);
    gemm_kernel<<<dim3(N_DIM / TM, LPAD / TN, B_DIM), 128, SMEM_BYTES>>>(
        (float*)d_out);
}